// round 14
// baseline (speedup 1.0000x reference)
#include <cuda_runtime.h>
#include <cuda_bf16.h>
#include <cuda_fp16.h>
#include <cstdint>

// Problem constants (fixed by the reference)
#define NN      10000
#define KNN     32
#define DG      256
#define ODIM    256
#define XSTRIDE 512   // 2*DG

// Scratch: fp16 transformed feature table + fp16 W
__device__ __half g_hh[NN * XSTRIDE];
__device__ __half g_Wh[2 * ODIM * DG];

__device__ __forceinline__ uint32_t smem_u32(const void* p) {
    uint32_t a;
    asm("{ .reg .u64 t; cvta.to.shared.u64 t, %1; cvt.u32.u64 %0, t; }"
        : "=r"(a) : "l"(p));
    return a;
}

__device__ __forceinline__ void ldm_x4(uint32_t* r, uint32_t addr) {
    asm volatile("ldmatrix.sync.aligned.m8n8.x4.shared.b16 {%0,%1,%2,%3}, [%4];"
                 : "=r"(r[0]), "=r"(r[1]), "=r"(r[2]), "=r"(r[3]) : "r"(addr));
}

__device__ __forceinline__ void mma_fp16(float* d, const uint32_t* a,
                                         const uint32_t* b) {
    asm volatile(
        "mma.sync.aligned.m16n8k16.row.col.f32.f16.f16.f32 "
        "{%0,%1,%2,%3}, {%4,%5,%6,%7}, {%8,%9}, {%0,%1,%2,%3};"
        : "+f"(d[0]), "+f"(d[1]), "+f"(d[2]), "+f"(d[3])
        : "r"(a[0]), "r"(a[1]), "r"(a[2]), "r"(a[3]), "r"(b[0]), "r"(b[1]));
}

__device__ __forceinline__ void cp_async16(uint32_t smem, const void* gptr) {
    asm volatile("cp.async.cg.shared.global [%0], [%1], 16;"
                 :: "r"(smem), "l"(gptr) : "memory");
}
__device__ __forceinline__ void cp_commit() {
    asm volatile("cp.async.commit_group;" ::: "memory");
}
__device__ __forceinline__ void cp_wait0() {
    asm volatile("cp.async.wait_group 0;" ::: "memory");
}

// unpack 8 halves (uint4) into 8 floats
__device__ __forceinline__ void h8_to_f8(uint4 u, float* f) {
    float2 p;
    p = __half22float2(*(__half2*)&u.x); f[0] = p.x; f[1] = p.y;
    p = __half22float2(*(__half2*)&u.y); f[2] = p.x; f[3] = p.y;
    p = __half22float2(*(__half2*)&u.z); f[4] = p.x; f[5] = p.y;
    p = __half22float2(*(__half2*)&u.w); f[6] = p.x; f[7] = p.y;
}

// ---------------------------------------------------------------------------
// Kernel 0: convert W1/W2 to fp16.
// ---------------------------------------------------------------------------
__global__ __launch_bounds__(256)
void wcvt_kernel(const float* __restrict__ W1, const float* __restrict__ W2) {
    int idx = blockIdx.x * 256 + threadIdx.x;
    int wlin = idx * 4;
    int g = wlin >= ODIM * DG;
    int off = wlin - g * ODIM * DG;
    const float* __restrict__ W = g ? W2 : W1;
    float4 v = *(const float4*)&W[off];
    __half2 p0 = __floats2half2_rn(v.x, v.y);
    __half2 p1 = __floats2half2_rn(v.z, v.w);
    *(uint2*)&g_Wh[wlin] = make_uint2(*(uint32_t*)&p0, *(uint32_t*)&p1);
}

// ---------------------------------------------------------------------------
// GEMM via HMMA fp16, fp32 accumulate, software-pipelined fills (proven R13).
// Block tile 64x256, 8 warps (2m x 4n). Grid (157, 2). Epilogue -> fp16 table.
// ---------------------------------------------------------------------------
#define STR 40   // fp16 per smem row (32 k + 8 pad): 80B stride, conflict-free

#define ABUF      (64 * STR * 2)                 // 5120
#define BBUF      (256 * STR * 2)                // 20480
#define DSM_A     0                               // 2 x ABUF
#define DSM_B     (2 * ABUF)                      // 10240, 2 x BBUF
#define DSM_FW    (DSM_B + 2 * BBUF)              // 51200
#define DSM_RED   (DSM_FW + 1024)                 // 52224
#define DSM_TOTAL (DSM_RED + 1024)                // 53248

__global__ __launch_bounds__(256)
void gemm_mma_kernel(const float* __restrict__ x,
                     const float* __restrict__ a1, const float* __restrict__ a2) {
    extern __shared__ char dsm[];
    __half* sA = (__half*)(dsm + DSM_A);
    float* sFW = (float*)(dsm + DSM_FW);
    float* red = (float*)(dsm + DSM_RED);

    const int t    = threadIdx.x;
    const int lane = t & 31;
    const int wid  = t >> 5;
    const int wm   = wid >> 2;     // 0..1
    const int wn   = wid & 3;      // 0..3
    const int g    = blockIdx.y;
    const int i0   = blockIdx.x * 64;
    const float* __restrict__ a = g ? a2 : a1;
    const __half* __restrict__ Wh = g_Wh + g * ODIM * DG;

    // ---- fused fw = softmax(a) ----
    float av = a[t];
    red[t] = av; __syncthreads();
    #pragma unroll
    for (int s = 128; s > 0; s >>= 1) {
        if (t < s) red[t] = fmaxf(red[t], red[t + s]);
        __syncthreads();
    }
    float amax = red[0]; __syncthreads();
    float e = expf(av - amax);
    red[t] = e; __syncthreads();
    #pragma unroll
    for (int s = 128; s > 0; s >>= 1) {
        if (t < s) red[t] += red[t + s];
        __syncthreads();
    }
    float esum = red[0]; __syncthreads();
    sFW[t] = e / esum;

    const uint32_t sAb = smem_u32(sA);
    const uint32_t sBb = smem_u32(dsm + DSM_B);
    const uint32_t aoff = (uint32_t)(((wm * 32 + (lane & 15)) * STR +
                                      ((lane >> 4) & 1) * 8) * 2);
    const uint32_t boff = (uint32_t)(((wn * 64 + (lane & 7) + ((lane >> 4) & 1) * 8) * STR +
                                      ((lane >> 3) & 1) * 8) * 2);

    float acc[2][8][4];
    #pragma unroll
    for (int mt = 0; mt < 2; ++mt)
        #pragma unroll
        for (int nt = 0; nt < 8; ++nt)
            #pragma unroll
            for (int q = 0; q < 4; ++q) acc[mt][nt][q] = 0.f;

    const int arow = t >> 2;
    const int akk  = (t & 3) * 8;
    const bool arow_ok = (i0 + arow) < NN;
    const float* __restrict__ xrow =
        x + (size_t)(i0 + arow) * XSTRIDE + g * DG + akk;
    const uint32_t aSts = (uint32_t)((arow * STR + akk) * 2);

    int brow[4], bkk[4];
    #pragma unroll
    for (int q = 0; q < 4; ++q) {
        int lin = q * 256 + t;
        brow[q] = lin >> 2;
        bkk[q]  = (lin & 3) * 8;
    }

    // ---- prologue: stage chunk 0 ----
    {
        #pragma unroll
        for (int q = 0; q < 4; ++q)
            cp_async16(sBb + (uint32_t)((brow[q] * STR + bkk[q]) * 2),
                       &Wh[(size_t)brow[q] * DG + bkk[q]]);
        cp_commit();
        float4 v0 = make_float4(0.f, 0.f, 0.f, 0.f);
        float4 v1 = make_float4(0.f, 0.f, 0.f, 0.f);
        if (arow_ok) {
            v0 = *(const float4*)(xrow);
            v1 = *(const float4*)(xrow + 4);
        }
        __half2 p0 = __floats2half2_rn(v0.x, v0.y);
        __half2 p1 = __floats2half2_rn(v0.z, v0.w);
        __half2 p2 = __floats2half2_rn(v1.x, v1.y);
        __half2 p3 = __floats2half2_rn(v1.z, v1.w);
        *(uint4*)(dsm + aSts) = make_uint4(
            *(uint32_t*)&p0, *(uint32_t*)&p1, *(uint32_t*)&p2, *(uint32_t*)&p3);
        cp_wait0();
    }
    __syncthreads();

    for (int c = 0; c < 8; ++c) {
        const int buf  = c & 1;
        const int nbuf = buf ^ 1;
        const bool pf = c < 7;
        float4 v0, v1;

        if (pf) {
            const int kn = (c + 1) * 32;
            #pragma unroll
            for (int q = 0; q < 4; ++q)
                cp_async16(sBb + (uint32_t)(nbuf * BBUF + (brow[q] * STR + bkk[q]) * 2),
                           &Wh[(size_t)brow[q] * DG + kn + bkk[q]]);
            cp_commit();
            if (arow_ok) {
                v0 = *(const float4*)(xrow + kn);
                v1 = *(const float4*)(xrow + kn + 4);
            } else {
                v0 = make_float4(0.f, 0.f, 0.f, 0.f);
                v1 = make_float4(0.f, 0.f, 0.f, 0.f);
            }
        }

        const uint32_t sA0 = sAb + buf * ABUF;
        const uint32_t sB0 = sBb + buf * BBUF;
        #pragma unroll
        for (int ks = 0; ks < 2; ++ks) {
            uint32_t ah[2][4];
            ldm_x4(ah[0], sA0 + aoff + ks * 32);
            ldm_x4(ah[1], sA0 + aoff + 16 * STR * 2 + ks * 32);
            #pragma unroll
            for (int nt2 = 0; nt2 < 4; ++nt2) {
                uint32_t bh[4];
                ldm_x4(bh, sB0 + boff + nt2 * 16 * STR * 2 + ks * 32);
                #pragma unroll
                for (int mt = 0; mt < 2; ++mt) {
                    mma_fp16(acc[mt][nt2 * 2],     ah[mt], bh);
                    mma_fp16(acc[mt][nt2 * 2 + 1], ah[mt], bh + 2);
                }
            }
        }

        if (pf) {
            __half2 p0 = __floats2half2_rn(v0.x, v0.y);
            __half2 p1 = __floats2half2_rn(v0.z, v0.w);
            __half2 p2 = __floats2half2_rn(v1.x, v1.y);
            __half2 p3 = __floats2half2_rn(v1.z, v1.w);
            *(uint4*)(dsm + nbuf * ABUF + aSts) = make_uint4(
                *(uint32_t*)&p0, *(uint32_t*)&p1, *(uint32_t*)&p2, *(uint32_t*)&p3);
            cp_wait0();
        }
        __syncthreads();
    }

    // ---- epilogue: scale by fw, clip, convert fp16, store ----
    #pragma unroll
    for (int mt = 0; mt < 2; ++mt) {
        int ra = i0 + wm * 32 + mt * 16 + (lane >> 2);
        int rb = ra + 8;
        #pragma unroll
        for (int nt = 0; nt < 8; ++nt) {
            int colg = wn * 64 + nt * 8 + (lane & 3) * 2;
            float f0 = sFW[colg], f1 = sFW[colg + 1];
            if (ra < NN) {
                float vx = fminf(1.f, fmaxf(-1.f, acc[mt][nt][0] * f0));
                float vy = fminf(1.f, fmaxf(-1.f, acc[mt][nt][1] * f1));
                *(__half2*)&g_hh[(size_t)ra * XSTRIDE + g * DG + colg] =
                    __floats2half2_rn(vx, vy);
            }
            if (rb < NN) {
                float vx = fminf(1.f, fmaxf(-1.f, acc[mt][nt][2] * f0));
                float vy = fminf(1.f, fmaxf(-1.f, acc[mt][nt][3] * f1));
                *(__half2*)&g_hh[(size_t)rb * XSTRIDE + g * DG + colg] =
                    __floats2half2_rn(vx, vy);
            }
        }
    }
}

// ---------------------------------------------------------------------------
// Attention v7: one block = 2 nodes x BOTH groups, 512 threads, 16 warps.
// Warp w: node = w>>3, group = (w>>2)&1, wl = w&3; 8 gathers/warp (MLP=8),
// half2 scoring. Graph indices loaded once per pair; block count 4x lower.
// ---------------------------------------------------------------------------
__global__ __launch_bounds__(512)
void attn_kernel(const int* __restrict__ graph, float* __restrict__ out) {
    const int i0 = blockIdx.x * 2;

    __shared__ int   idxs[2 * KNN];
    __shared__ float score[4 * KNN];   // [(n*2+g)*KNN + j]
    __shared__ float agg[16][DG];      // 16KB

    const int t    = threadIdx.x;
    const int lane = t & 31;
    const int w    = t >> 5;
    const int n    = w >> 3;           // node within pair
    const int grp  = (w >> 2) & 1;     // group
    const int wl   = w & 3;            // warp within (node, group)
    const int sidx = (n * 2 + grp) * KNN;

    if (t < 2 * KNN) idxs[t] = __ldg(&graph[(size_t)i0 * KNN + t]);
    __syncthreads();

    const __half* __restrict__ base = g_hh + grp * DG + lane * 8;

    // self row (raw fp16)
    uint4 ovu = *(const uint4*)(base + (size_t)(i0 + n) * XSTRIDE);
    const __half2* ov2 = (const __half2*)&ovu;

    // gather 8 neighbor rows (512B contiguous each, MLP=8)
    uint4 nbu[8];
    #pragma unroll
    for (int r = 0; r < 8; ++r)
        nbu[r] = __ldcg((const uint4*)(base +
                    (size_t)idxs[n * KNN + wl + 4 * r] * XSTRIDE));

    // scores in half2
    #pragma unroll
    for (int r = 0; r < 8; ++r) {
        const __half2* nb2 = (const __half2*)&nbu[r];
        __half2 acc2 = __float2half2_rn(0.f);
        #pragma unroll
        for (int d = 0; d < 4; ++d) {
            __half2 df = __hsub2(ov2[d], nb2[d]);
            acc2 = __hfma2(df, df, acc2);
        }
        float2 sf = __half22float2(acc2);
        float s = sf.x + sf.y;
        #pragma unroll
        for (int off = 16; off; off >>= 1) s += __shfl_xor_sync(0xffffffffu, s, off);
        if (lane == 0) score[sidx + wl + 4 * r] = -s;
    }
    __syncthreads();

    // softmax: 4 warps, warp j handles (node j>>1, group j&1)
    if (t < 4 * KNN) {
        float s = score[t];
        float m = s;
        #pragma unroll
        for (int off = 16; off; off >>= 1) m = fmaxf(m, __shfl_xor_sync(0xffffffffu, m, off));
        float e = __expf(s - m);
        float sum = e;
        #pragma unroll
        for (int off = 16; off; off >>= 1) sum += __shfl_xor_sync(0xffffffffu, sum, off);
        score[t] = e / sum;
    }
    __syncthreads();

    // weighted partial aggregate (fp32), 8 neighbors per warp
    float acc[8];
    #pragma unroll
    for (int d = 0; d < 8; ++d) acc[d] = 0.f;
    #pragma unroll
    for (int r = 0; r < 8; ++r) {
        float f[8];
        h8_to_f8(nbu[r], f);
        float wt = score[sidx + wl + 4 * r];
        #pragma unroll
        for (int d = 0; d < 8; ++d)
            acc[d] = fmaf(wt, f[d], acc[d]);
    }
    *(float4*)&agg[w][lane * 8]     = make_float4(acc[0], acc[1], acc[2], acc[3]);
    *(float4*)&agg[w][lane * 8 + 4] = make_float4(acc[4], acc[5], acc[6], acc[7]);
    __syncthreads();

    // final cross-warp column sums: 1024 outputs, 2 per thread
    #pragma unroll
    for (int p = 0; p < 2; ++p) {
        int o   = t + p * 512;
        int nn  = o >> 9;           // 0..1
        int gg  = (o >> 8) & 1;     // 0..1
        int col = o & 255;
        int rb  = nn * 8 + gg * 4;
        float s = (agg[rb][col] + agg[rb + 1][col]) +
                  (agg[rb + 2][col] + agg[rb + 3][col]);
        out[(size_t)(i0 + nn) * XSTRIDE + gg * DG + col] = s;
    }
}

// ---------------------------------------------------------------------------
// Launch
// ---------------------------------------------------------------------------
extern "C" void kernel_launch(void* const* d_in, const int* in_sizes, int n_in,
                              void* d_out, int out_size) {
    const float* x     = (const float*)d_in[0];
    const float* W1    = (const float*)d_in[1];
    const float* a1    = (const float*)d_in[2];
    const float* W2    = (const float*)d_in[3];
    const float* a2    = (const float*)d_in[4];
    const int*   graph = (const int*)d_in[5];
    float* out = (float*)d_out;

    static int smem_set = 0;
    if (!smem_set) {
        cudaFuncSetAttribute(gemm_mma_kernel,
                             cudaFuncAttributeMaxDynamicSharedMemorySize, DSM_TOTAL);
        smem_set = 1;
    }

    wcvt_kernel<<<2 * ODIM * DG / (256 * 4), 256>>>(W1, W2);

    dim3 ggrid((NN + 63) / 64, 2);
    gemm_mma_kernel<<<ggrid, 256, DSM_TOTAL>>>(x, a1, a2);

    attn_kernel<<<NN / 2, 512>>>(graph, out);
}

// round 15
// speedup vs baseline: 1.0273x; 1.0273x over previous
#include <cuda_runtime.h>
#include <cuda_bf16.h>
#include <cuda_fp16.h>
#include <cstdint>

// Problem constants (fixed by the reference)
#define NN      10000
#define KNN     32
#define DG      256
#define ODIM    256
#define XSTRIDE 512   // 2*DG

// Scratch: fp16 transformed feature table + fp16 W
__device__ __half g_hh[NN * XSTRIDE];
__device__ __half g_Wh[2 * ODIM * DG];

__device__ __forceinline__ uint32_t smem_u32(const void* p) {
    uint32_t a;
    asm("{ .reg .u64 t; cvta.to.shared.u64 t, %1; cvt.u32.u64 %0, t; }"
        : "=r"(a) : "l"(p));
    return a;
}

__device__ __forceinline__ void ldm_x4(uint32_t* r, uint32_t addr) {
    asm volatile("ldmatrix.sync.aligned.m8n8.x4.shared.b16 {%0,%1,%2,%3}, [%4];"
                 : "=r"(r[0]), "=r"(r[1]), "=r"(r[2]), "=r"(r[3]) : "r"(addr));
}

__device__ __forceinline__ void mma_fp16(float* d, const uint32_t* a,
                                         const uint32_t* b) {
    asm volatile(
        "mma.sync.aligned.m16n8k16.row.col.f32.f16.f16.f32 "
        "{%0,%1,%2,%3}, {%4,%5,%6,%7}, {%8,%9}, {%0,%1,%2,%3};"
        : "+f"(d[0]), "+f"(d[1]), "+f"(d[2]), "+f"(d[3])
        : "r"(a[0]), "r"(a[1]), "r"(a[2]), "r"(a[3]), "r"(b[0]), "r"(b[1]));
}

__device__ __forceinline__ void cp_async16(uint32_t smem, const void* gptr) {
    asm volatile("cp.async.cg.shared.global [%0], [%1], 16;"
                 :: "r"(smem), "l"(gptr) : "memory");
}
__device__ __forceinline__ void cp_commit() {
    asm volatile("cp.async.commit_group;" ::: "memory");
}
__device__ __forceinline__ void cp_wait0() {
    asm volatile("cp.async.wait_group 0;" ::: "memory");
}

// unpack 8 halves (uint4) into 8 floats
__device__ __forceinline__ void h8_to_f8(uint4 u, float* f) {
    float2 p;
    p = __half22float2(*(__half2*)&u.x); f[0] = p.x; f[1] = p.y;
    p = __half22float2(*(__half2*)&u.y); f[2] = p.x; f[3] = p.y;
    p = __half22float2(*(__half2*)&u.z); f[4] = p.x; f[5] = p.y;
    p = __half22float2(*(__half2*)&u.w); f[6] = p.x; f[7] = p.y;
}

// ---------------------------------------------------------------------------
// Kernel 0: convert W1/W2 to fp16.
// ---------------------------------------------------------------------------
__global__ __launch_bounds__(256)
void wcvt_kernel(const float* __restrict__ W1, const float* __restrict__ W2) {
    int idx = blockIdx.x * 256 + threadIdx.x;
    int wlin = idx * 4;
    int g = wlin >= ODIM * DG;
    int off = wlin - g * ODIM * DG;
    const float* __restrict__ W = g ? W2 : W1;
    float4 v = *(const float4*)&W[off];
    __half2 p0 = __floats2half2_rn(v.x, v.y);
    __half2 p1 = __floats2half2_rn(v.z, v.w);
    *(uint2*)&g_Wh[wlin] = make_uint2(*(uint32_t*)&p0, *(uint32_t*)&p1);
}

// ---------------------------------------------------------------------------
// GEMM via HMMA fp16, fp32 accumulate, software-pipelined fills.
// Block tile 128x256 (1.07 waves: grid (79,2) = 158 blocks on 148 SMs),
// 8 warps (2m x 4n), warp tile 64x64. Epilogue -> fp16 table.
// ---------------------------------------------------------------------------
#define STR 40   // fp16 per smem row (32 k + 8 pad): 80B stride, conflict-free
#define BM  128

#define ABUF      (BM * STR * 2)                  // 10240
#define BBUF      (256 * STR * 2)                 // 20480
#define DSM_A     0                                // 2 x ABUF
#define DSM_B     (2 * ABUF)                       // 20480, 2 x BBUF
#define DSM_FW    (DSM_B + 2 * BBUF)               // 61440
#define DSM_RED   (DSM_FW + 1024)                  // 62464
#define DSM_TOTAL (DSM_RED + 1024)                 // 63488

__global__ __launch_bounds__(256)
void gemm_mma_kernel(const float* __restrict__ x,
                     const float* __restrict__ a1, const float* __restrict__ a2) {
    extern __shared__ char dsm[];
    float* sFW = (float*)(dsm + DSM_FW);
    float* red = (float*)(dsm + DSM_RED);

    const int t    = threadIdx.x;
    const int lane = t & 31;
    const int wid  = t >> 5;
    const int wm   = wid >> 2;     // 0..1 (64 rows each)
    const int wn   = wid & 3;      // 0..3 (64 cols each)
    const int g    = blockIdx.y;
    const int i0   = blockIdx.x * BM;
    const float* __restrict__ a = g ? a2 : a1;
    const __half* __restrict__ Wh = g_Wh + g * ODIM * DG;

    // ---- fused fw = softmax(a) ----
    float av = a[t];
    red[t] = av; __syncthreads();
    #pragma unroll
    for (int s = 128; s > 0; s >>= 1) {
        if (t < s) red[t] = fmaxf(red[t], red[t + s]);
        __syncthreads();
    }
    float amax = red[0]; __syncthreads();
    float e = expf(av - amax);
    red[t] = e; __syncthreads();
    #pragma unroll
    for (int s = 128; s > 0; s >>= 1) {
        if (t < s) red[t] += red[t + s];
        __syncthreads();
    }
    float esum = red[0]; __syncthreads();
    sFW[t] = e / esum;

    const uint32_t sAb = smem_u32(dsm + DSM_A);
    const uint32_t sBb = smem_u32(dsm + DSM_B);
    const uint32_t aoff = (uint32_t)(((wm * 64 + (lane & 15)) * STR +
                                      ((lane >> 4) & 1) * 8) * 2);
    const uint32_t boff = (uint32_t)(((wn * 64 + (lane & 7) + ((lane >> 4) & 1) * 8) * STR +
                                      ((lane >> 3) & 1) * 8) * 2);

    float acc[4][8][4];
    #pragma unroll
    for (int mt = 0; mt < 4; ++mt)
        #pragma unroll
        for (int nt = 0; nt < 8; ++nt)
            #pragma unroll
            for (int q = 0; q < 4; ++q) acc[mt][nt][q] = 0.f;

    // A fill: 2 segments per thread (lin = q*256+t -> row = lin>>2, kseg)
    int arw[2], akk[2];
    bool aok[2];
    const float* xp[2];
    uint32_t aSts[2];
    #pragma unroll
    for (int q = 0; q < 2; ++q) {
        int lin = q * 256 + t;
        arw[q] = lin >> 1;                 // 0..255? no: 512 lins / 128 rows
        // 128 rows x 4 segments = 512 units; row = lin>>2, seg = lin&3
        arw[q] = lin >> 2;
        akk[q] = (lin & 3) * 8;
        aok[q] = (i0 + arw[q]) < NN;
        xp[q]  = x + (size_t)(i0 + arw[q]) * XSTRIDE + g * DG + akk[q];
        aSts[q] = (uint32_t)((arw[q] * STR + akk[q]) * 2);
    }

    // B fill: 4 segments per thread
    int brow[4], bkk[4];
    #pragma unroll
    for (int q = 0; q < 4; ++q) {
        int lin = q * 256 + t;
        brow[q] = lin >> 2;
        bkk[q]  = (lin & 3) * 8;
    }

    // ---- prologue: stage chunk 0 ----
    {
        #pragma unroll
        for (int q = 0; q < 4; ++q)
            cp_async16(sBb + (uint32_t)((brow[q] * STR + bkk[q]) * 2),
                       &Wh[(size_t)brow[q] * DG + bkk[q]]);
        cp_commit();
        #pragma unroll
        for (int q = 0; q < 2; ++q) {
            float4 v0 = make_float4(0.f, 0.f, 0.f, 0.f);
            float4 v1 = make_float4(0.f, 0.f, 0.f, 0.f);
            if (aok[q]) {
                v0 = *(const float4*)(xp[q]);
                v1 = *(const float4*)(xp[q] + 4);
            }
            __half2 p0 = __floats2half2_rn(v0.x, v0.y);
            __half2 p1 = __floats2half2_rn(v0.z, v0.w);
            __half2 p2 = __floats2half2_rn(v1.x, v1.y);
            __half2 p3 = __floats2half2_rn(v1.z, v1.w);
            *(uint4*)(dsm + aSts[q]) = make_uint4(
                *(uint32_t*)&p0, *(uint32_t*)&p1, *(uint32_t*)&p2, *(uint32_t*)&p3);
        }
        cp_wait0();
    }
    __syncthreads();

    for (int c = 0; c < 8; ++c) {
        const int buf  = c & 1;
        const int nbuf = buf ^ 1;
        const bool pf = c < 7;
        float4 v0[2], v1[2];

        // ---- prefetch chunk c+1 ----
        if (pf) {
            const int kn = (c + 1) * 32;
            #pragma unroll
            for (int q = 0; q < 4; ++q)
                cp_async16(sBb + (uint32_t)(nbuf * BBUF + (brow[q] * STR + bkk[q]) * 2),
                           &Wh[(size_t)brow[q] * DG + kn + bkk[q]]);
            cp_commit();
            #pragma unroll
            for (int q = 0; q < 2; ++q) {
                if (aok[q]) {
                    v0[q] = *(const float4*)(xp[q] + kn);
                    v1[q] = *(const float4*)(xp[q] + kn + 4);
                } else {
                    v0[q] = make_float4(0.f, 0.f, 0.f, 0.f);
                    v1[q] = make_float4(0.f, 0.f, 0.f, 0.f);
                }
            }
        }

        // ---- MMA on current buffers ----
        const uint32_t sA0 = sAb + buf * ABUF;
        const uint32_t sB0 = sBb + buf * BBUF;
        #pragma unroll
        for (int ks = 0; ks < 2; ++ks) {
            uint32_t ah[4][4];
            #pragma unroll
            for (int mt = 0; mt < 4; ++mt)
                ldm_x4(ah[mt], sA0 + aoff + mt * 16 * STR * 2 + ks * 32);
            #pragma unroll
            for (int nt2 = 0; nt2 < 4; ++nt2) {
                uint32_t bh[4];
                ldm_x4(bh, sB0 + boff + nt2 * 16 * STR * 2 + ks * 32);
                #pragma unroll
                for (int mt = 0; mt < 4; ++mt) {
                    mma_fp16(acc[mt][nt2 * 2],     ah[mt], bh);
                    mma_fp16(acc[mt][nt2 * 2 + 1], ah[mt], bh + 2);
                }
            }
        }

        // ---- store prefetched A into next buffer ----
        if (pf) {
            #pragma unroll
            for (int q = 0; q < 2; ++q) {
                __half2 p0 = __floats2half2_rn(v0[q].x, v0[q].y);
                __half2 p1 = __floats2half2_rn(v0[q].z, v0[q].w);
                __half2 p2 = __floats2half2_rn(v1[q].x, v1[q].y);
                __half2 p3 = __floats2half2_rn(v1[q].z, v1[q].w);
                *(uint4*)(dsm + nbuf * ABUF + aSts[q]) = make_uint4(
                    *(uint32_t*)&p0, *(uint32_t*)&p1, *(uint32_t*)&p2, *(uint32_t*)&p3);
            }
            cp_wait0();
        }
        __syncthreads();
    }

    // ---- epilogue: scale by fw, clip, convert fp16, store ----
    #pragma unroll
    for (int mt = 0; mt < 4; ++mt) {
        int ra = i0 + wm * 64 + mt * 16 + (lane >> 2);
        int rb = ra + 8;
        #pragma unroll
        for (int nt = 0; nt < 8; ++nt) {
            int colg = wn * 64 + nt * 8 + (lane & 3) * 2;
            float f0 = sFW[colg], f1 = sFW[colg + 1];
            if (ra < NN) {
                float vx = fminf(1.f, fmaxf(-1.f, acc[mt][nt][0] * f0));
                float vy = fminf(1.f, fmaxf(-1.f, acc[mt][nt][1] * f1));
                *(__half2*)&g_hh[(size_t)ra * XSTRIDE + g * DG + colg] =
                    __floats2half2_rn(vx, vy);
            }
            if (rb < NN) {
                float vx = fminf(1.f, fmaxf(-1.f, acc[mt][nt][2] * f0));
                float vy = fminf(1.f, fmaxf(-1.f, acc[mt][nt][3] * f1));
                *(__half2*)&g_hh[(size_t)rb * XSTRIDE + g * DG + colg] =
                    __floats2half2_rn(vx, vy);
            }
        }
    }
}

// ---------------------------------------------------------------------------
// Attention v6 (proven, 72.1us): 2 nodes per block (grid 5000 x 2), 256 thr.
// Warp w serves node (w>>2); 8 neighbor rows per warp (MLP=8, raw fp16).
// Scores in half2.
// ---------------------------------------------------------------------------
__global__ __launch_bounds__(256)
void attn_kernel(const int* __restrict__ graph, float* __restrict__ out) {
    const int i0 = blockIdx.x * 2;
    const int g  = blockIdx.y;

    __shared__ int   idxs[2 * KNN];
    __shared__ float score[2 * KNN];
    __shared__ float agg[8][DG];    // rows 0-3: node 0, rows 4-7: node 1

    const int t    = threadIdx.x;
    const int lane = t & 31;
    const int w    = t >> 5;
    const int n    = w >> 2;        // node within pair
    const int wl   = w & 3;         // warp within node

    if (t < 2 * KNN) idxs[t] = __ldg(&graph[(size_t)i0 * KNN + t]);
    __syncthreads();

    const __half* __restrict__ base = g_hh + g * DG + lane * 8;

    // self row (raw fp16)
    uint4 ovu = *(const uint4*)(base + (size_t)(i0 + n) * XSTRIDE);
    const __half2* ov2 = (const __half2*)&ovu;

    // gather 8 neighbor rows (512B contiguous each, MLP=8)
    uint4 nbu[8];
    #pragma unroll
    for (int r = 0; r < 8; ++r)
        nbu[r] = __ldcg((const uint4*)(base +
                    (size_t)idxs[n * KNN + wl + 4 * r] * XSTRIDE));

    // scores in half2
    #pragma unroll
    for (int r = 0; r < 8; ++r) {
        const __half2* nb2 = (const __half2*)&nbu[r];
        __half2 acc2 = __float2half2_rn(0.f);
        #pragma unroll
        for (int d = 0; d < 4; ++d) {
            __half2 df = __hsub2(ov2[d], nb2[d]);
            acc2 = __hfma2(df, df, acc2);
        }
        float2 sf = __half22float2(acc2);
        float s = sf.x + sf.y;
        #pragma unroll
        for (int off = 16; off; off >>= 1) s += __shfl_xor_sync(0xffffffffu, s, off);
        if (lane == 0) score[n * KNN + wl + 4 * r] = -s;
    }
    __syncthreads();

    // softmax: warp 0 -> node 0, warp 1 -> node 1
    if (t < 2 * KNN) {
        float s = score[t];
        float m = s;
        #pragma unroll
        for (int off = 16; off; off >>= 1) m = fmaxf(m, __shfl_xor_sync(0xffffffffu, m, off));
        float e = __expf(s - m);
        float sum = e;
        #pragma unroll
        for (int off = 16; off; off >>= 1) sum += __shfl_xor_sync(0xffffffffu, sum, off);
        score[t] = e / sum;
    }
    __syncthreads();

    // weighted partial aggregate (fp32)
    float acc[8];
    #pragma unroll
    for (int d = 0; d < 8; ++d) acc[d] = 0.f;
    #pragma unroll
    for (int r = 0; r < 8; ++r) {
        float f[8];
        h8_to_f8(nbu[r], f);
        float wt = score[n * KNN + wl + 4 * r];
        #pragma unroll
        for (int d = 0; d < 8; ++d)
            acc[d] = fmaf(wt, f[d], acc[d]);
    }
    *(float4*)&agg[w][lane * 8]     = make_float4(acc[0], acc[1], acc[2], acc[3]);
    *(float4*)&agg[w][lane * 8 + 4] = make_float4(acc[4], acc[5], acc[6], acc[7]);
    __syncthreads();

    // cross-warp column sums + store (thread t = column t, both nodes)
    float s0 = (agg[0][t] + agg[1][t]) + (agg[2][t] + agg[3][t]);
    float s1 = (agg[4][t] + agg[5][t]) + (agg[6][t] + agg[7][t]);
    out[(size_t)i0 * XSTRIDE + g * DG + t] = s0;
    out[(size_t)(i0 + 1) * XSTRIDE + g * DG + t] = s1;
}

// ---------------------------------------------------------------------------
// Launch
// ---------------------------------------------------------------------------
extern "C" void kernel_launch(void* const* d_in, const int* in_sizes, int n_in,
                              void* d_out, int out_size) {
    const float* x     = (const float*)d_in[0];
    const float* W1    = (const float*)d_in[1];
    const float* a1    = (const float*)d_in[2];
    const float* W2    = (const float*)d_in[3];
    const float* a2    = (const float*)d_in[4];
    const int*   graph = (const int*)d_in[5];
    float* out = (float*)d_out;

    static int smem_set = 0;
    if (!smem_set) {
        cudaFuncSetAttribute(gemm_mma_kernel,
                             cudaFuncAttributeMaxDynamicSharedMemorySize, DSM_TOTAL);
        smem_set = 1;
    }

    wcvt_kernel<<<2 * ODIM * DG / (256 * 4), 256>>>(W1, W2);

    dim3 ggrid((NN + BM - 1) / BM, 2);
    gemm_mma_kernel<<<ggrid, 256, DSM_TOTAL>>>(x, a1, a2);

    dim3 agrid(NN / 2, 2);
    attn_kernel<<<agrid, 256>>>(graph, out);
}